// round 15
// baseline (speedup 1.0000x reference)
#include <cuda_runtime.h>

#define Hh 2048
#define Ww 2048
#define HW (Hh * Ww)
#define TX 32
#define TY 16
#define GBX (Ww / TX)      // 64
#define GBY (Hh / TY)      // 128
#define P1X 34
#define P1Y 18
#define P1N (P1X * P1Y)    // 612 : 1-halo region (props / state)
#define SRCX 40            // padded, 16B-aligned staging for src (2-halo + vec align)
#define SRCY 20

// fast exp2: exactly the MUFU.EX2 instruction, no compiler-flag dependence
__device__ __forceinline__ float ex2(float x) {
    float r;
    asm("ex2.approx.f32 %0, %1;" : "=f"(r) : "f"(x));
    return r;
}

// ---------------------------------------------------------------------------
// Fully fused step. R15 structural change: EARLY-STORE raw exps with a
// running sum (collapses the 9-exp live range), inv folded into the 3 state
// planes (m*inv, mx*inv, my*inv — gather is algebraically identical), and
// __launch_bounds__(256,6) to get 6 blocks/SM at 42 regs. The R7 spill
// happened because all 9 exps + inv-products were live at once; that live
// set no longer exists.
//  - global renormalization skipped (softmax sums to 1, MOVES are shifts)
//  - 4 conv kernels combined to 2 (k0+k1, 0.5*(k2+k3))
// ---------------------------------------------------------------------------
__global__ void __launch_bounds__(256, 6) step_kernel(
    const float* __restrict__ mass, const float* __restrict__ mom,
    const float* __restrict__ force, const float* __restrict__ A,
    const float* __restrict__ kern, float* __restrict__ out)
{
    __shared__ float  s_src[SRCY * SRCX];
    __shared__ float  sp[9][P1N];   // RAW (unnormalized) shifted exps
    __shared__ float  s_m[P1N];     // mass * inv
    __shared__ float2 smxy[P1N];    // (mx*inv, my*inv)
    __shared__ float  s_w[19];      // w0[9], w1[9], kc

    const int tid = threadIdx.x;
    const int bx = blockIdx.x, by = blockIdx.y;
    const int tx0 = bx * TX;
    const int ty0 = by * TY;
    const bool interior = (bx >= 1) & (bx <= GBX - 2) & (by >= 1) & (by <= GBY - 2);

    if (tid == 0) {
        float ssum = 0.0f;
        #pragma unroll
        for (int j = 0; j < 36; ++j) ssum += fabsf(kern[j]);
        s_w[18] = 1.0f / ssum;
        #pragma unroll
        for (int j = 0; j < 9; ++j) {
            s_w[j]     = kern[j] + kern[9 + j];
            s_w[9 + j] = 0.5f * (kern[18 + j] + kern[27 + j]);
        }
    }

    // ---- Phase A: stage src = A*mass + |force| over 40x20 (2-halo, padded) ----
    if (interior) {
        const float4* m4 = (const float4*)mass;
        const float4* a4 = (const float4*)A;
        const float4* f4 = (const float4*)force;
        const int c0 = (tx0 - 4) >> 2;
        for (int i = tid; i < SRCY * SRCX / 4; i += 256) {   // 200 float4
            int r = i / (SRCX / 4), c = i - r * (SRCX / 4);
            int g4 = (ty0 - 2 + r) * (Ww / 4) + c0 + c;
            float4 m = m4[g4], a = a4[g4];
            float4 fx = f4[g4], fy = f4[HW / 4 + g4];
            float hx = fmaf(fx.x, fx.x, fy.x * fy.x);
            float hy = fmaf(fx.y, fx.y, fy.y * fy.y);
            float hz = fmaf(fx.z, fx.z, fy.z * fy.z);
            float hw = fmaf(fx.w, fx.w, fy.w * fy.w);
            float4 s;
            s.x = fmaf(a.x, m.x, hx * rsqrtf(fmaxf(hx, 1e-38f)));
            s.y = fmaf(a.y, m.y, hy * rsqrtf(fmaxf(hy, 1e-38f)));
            s.z = fmaf(a.z, m.z, hz * rsqrtf(fmaxf(hz, 1e-38f)));
            s.w = fmaf(a.w, m.w, hw * rsqrtf(fmaxf(hw, 1e-38f)));
            ((float4*)s_src)[i] = s;
        }
    } else {
        for (int i = tid; i < SRCY * SRCX; i += 256) {
            int r = i / SRCX, c = i - r * SRCX;
            int gx = tx0 - 4 + c; if (gx < 0) gx += Ww; else if (gx >= Ww) gx -= Ww;
            int gy = ty0 - 2 + r; if (gy < 0) gy += Hh; else if (gy >= Hh) gy -= Hh;
            int g = gy * Ww + gx;
            float m = mass[g], a = A[g];
            float fx = force[g], fy = force[HW + g];
            float h = fmaf(fx, fx, fy * fy);
            s_src[i] = fmaf(a, m, h * rsqrtf(fmaxf(h, 1e-38f)));
        }
    }
    __syncthreads();

    const float kc = s_w[18];
    // temp*log2(e) folded: exp(0.1*x) == exp2(C*x)
    const float CT   = 0.1f * 1.4426950408889634f;
    const float SQ2T = 0.70710678118654752f * 0.1f * 1.4426950408889634f;

    // ---- Phase B: physics + softmax for the 1-halo region (34x18) ----
    for (int s = tid; s < P1N; s += 256) {
        int sy = s / P1X, sx = s - sy * P1X;
        int p2 = (sy + 1) * SRCX + sx + 3;

        float nf0 = 0.0f, nf1 = 0.0f;
        #pragma unroll
        for (int r = 0; r < 3; ++r)
            #pragma unroll
            for (int c = 0; c < 3; ++c) {
                float v = s_src[p2 + (r - 1) * SRCX + (c - 1)];
                nf0 = fmaf(v, s_w[r * 3 + c], nf0);
                nf1 = fmaf(v, s_w[9 + r * 3 + c], nf1);
            }

        int g;
        if (interior) {
            g = (ty0 + sy - 1) * Ww + tx0 + sx - 1;
        } else {
            int gx = tx0 + sx - 1; if (gx < 0) gx += Ww; else if (gx >= Ww) gx -= Ww;
            int gy = ty0 + sy - 1; if (gy < 0) gy += Hh; else if (gy >= Hh) gy -= Hh;
            g = gy * Ww + gx;
        }

        float fx = force[g], fy = force[HW + g];
        float fnx = fx + (nf0 - fx) * kc;
        float fny = fy + (nf1 - fy) * kc;
        float ms = mass[g];

        bool alive = !(ms < 1e-8f);
        float mnx = alive ? (mom[g] + fnx)      : 0.0f;
        float mny = alive ? (mom[HW + g] + fny) : 0.0f;
        float inv_ms = __fdividef(1.0f, ms);
        float vx = alive ? (mnx * inv_ms) : 0.0f;
        float vy = alive ? (mny * inv_ms) : 0.0f;

        if (sx >= 1 && sx <= TX && sy >= 1 && sy <= TY) {
            out[3 * HW + g] = fnx;
            out[4 * HW + g] = fny;
        }

        // base-2 logits: set {l0,l1,l2,l3,0,-l3,-l2,-l1,-l0}
        float sv = SQ2T * vx, sw = SQ2T * vy;
        float l0 = sv + sw;
        float l1 = CT * vy;
        float l2 = sw - sv;
        float l3 = CT * vx;

        float mx = fmaxf(fmaxf(fabsf(l0), fabsf(l1)), fmaxf(fabsf(l2), fabsf(l3)));
        // early-store each raw exp; only the running sum stays live
        float sum, e;
        e = ex2(l0 - mx);  sp[0][s] = e; sum  = e;
        e = ex2(l1 - mx);  sp[1][s] = e; sum += e;
        e = ex2(l2 - mx);  sp[2][s] = e; sum += e;
        e = ex2(l3 - mx);  sp[3][s] = e; sum += e;
        e = ex2(-mx);      sp[4][s] = e; sum += e;
        e = ex2(-l3 - mx); sp[5][s] = e; sum += e;
        e = ex2(-l2 - mx); sp[6][s] = e; sum += e;
        e = ex2(-l1 - mx); sp[7][s] = e; sum += e;
        e = ex2(-l0 - mx); sp[8][s] = e; sum += e;

        float inv = __fdividef(1.0f, sum);
        s_m[s]  = ms * inv;
        smxy[s] = make_float2(mnx * inv, mny * inv);
    }
    __syncthreads();

    // ---- Phase C: 3x3 gather, 2-row strip per thread, float2 state reads ----
    // props are raw exps; state planes carry the 1/sum normalization.
    {
        const int ltx = tid & 31;
        const int lty = tid >> 5;
        const int oyA = lty * 2;
        float amA = 0.f, axA = 0.f, ayA = 0.f;
        float amB = 0.f, axB = 0.f, ayB = 0.f;

        #pragma unroll
        for (int r = 0; r < 4; ++r) {
            int rb = (oyA + r) * P1X + ltx;
            float  qm0 = s_m[rb], qm1 = s_m[rb + 1], qm2 = s_m[rb + 2];
            float2 q0 = smxy[rb], q1 = smxy[rb + 1], q2 = smxy[rb + 2];

            if (r <= 2) {   // pixel A, dy = r-1, plane base (2-r)*3
                float p;
                p = sp[(2 - r) * 3 + 0][rb + 2];
                amA = fmaf(qm2, p, amA); axA = fmaf(q2.x, p, axA); ayA = fmaf(q2.y, p, ayA);
                p = sp[(2 - r) * 3 + 1][rb + 1];
                amA = fmaf(qm1, p, amA); axA = fmaf(q1.x, p, axA); ayA = fmaf(q1.y, p, ayA);
                p = sp[(2 - r) * 3 + 2][rb];
                amA = fmaf(qm0, p, amA); axA = fmaf(q0.x, p, axA); ayA = fmaf(q0.y, p, ayA);
            }
            if (r >= 1) {   // pixel B, dy = r-2, plane base (3-r)*3
                float p;
                p = sp[(3 - r) * 3 + 0][rb + 2];
                amB = fmaf(qm2, p, amB); axB = fmaf(q2.x, p, axB); ayB = fmaf(q2.y, p, ayB);
                p = sp[(3 - r) * 3 + 1][rb + 1];
                amB = fmaf(qm1, p, amB); axB = fmaf(q1.x, p, axB); ayB = fmaf(q1.y, p, ayB);
                p = sp[(3 - r) * 3 + 2][rb];
                amB = fmaf(qm0, p, amB); axB = fmaf(q0.x, p, axB); ayB = fmaf(q0.y, p, ayB);
            }
        }

        int gA = (ty0 + oyA) * Ww + tx0 + ltx;
        out[gA]               = amA;
        out[HW + gA]          = axA;
        out[2 * HW + gA]      = ayA;
        out[gA + Ww]          = amB;
        out[HW + gA + Ww]     = axB;
        out[2 * HW + gA + Ww] = ayB;
    }
}

// ---------------------------------------------------------------------------
extern "C" void kernel_launch(void* const* d_in, const int* in_sizes, int n_in,
                              void* d_out, int out_size) {
    const float* mass = (const float*)d_in[0];   // (1,1,H,W)
    const float* mom  = (const float*)d_in[1];   // (2,1,H,W)
    const float* forc = (const float*)d_in[2];   // (2,1,H,W)
    const float* A    = (const float*)d_in[3];   // (1,1,H,W)
    const float* kern = (const float*)d_in[4];   // (4,1,3,3)
    float* out = (float*)d_out;                  // [new_mass | new_mom(2) | force(2)]

    dim3 grid(GBX, GBY);
    step_kernel<<<grid, 256>>>(mass, mom, forc, A, kern, out);
}

// round 16
// speedup vs baseline: 1.1835x; 1.1835x over previous
#include <cuda_runtime.h>

#define Hh 2048
#define Ww 2048
#define HW (Hh * Ww)
#define TX 32
#define TY 16
#define GBX (Ww / TX)      // 64
#define GBY (Hh / TY)      // 128
#define P1X 34
#define P1Y 18
#define P1N (P1X * P1Y)    // 612 : 1-halo region (props / state)
#define SRCX 40            // padded, 16B-aligned staging for src (2-halo + vec align)
#define SRCY 20

// fast exp2: exactly the MUFU.EX2 instruction, no compiler-flag dependence
__device__ __forceinline__ float ex2(float x) {
    float r;
    asm("ex2.approx.f32 %0, %1;" : "=f"(r) : "f"(x));
    return r;
}

// ---------------------------------------------------------------------------
// Fully fused step (R14 base = best kernel time 73.5us).
// R16 change: prefetch mom into smxy during phase A (batched, high-MLP)
// so phase B's mid-chain cold LDGs become 29-cyc LDS hits. smxy is reused:
// A writes mom, B reads it then overwrites with (mnx,mny). Same thread owns
// the same s in A and B, so the existing sync suffices.
// Locked lessons: 40-warp operating point (NO block caps — R7/R15 spills),
// conv weights in registers, plane-major props, scalar 2-row phase C.
//  - global renormalization skipped (softmax sums to 1, MOVES are shifts)
//  - 4 conv kernels combined to 2 (k0+k1, 0.5*(k2+k3))
// ---------------------------------------------------------------------------
__global__ void __launch_bounds__(256) step_kernel(
    const float* __restrict__ mass, const float* __restrict__ mom,
    const float* __restrict__ force, const float* __restrict__ A,
    const float* __restrict__ kern, float* __restrict__ out)
{
    __shared__ float  s_src[SRCY * SRCX];
    __shared__ float  sp[9][P1N];   // normalized propagation weights
    __shared__ float  s_m[P1N];     // mass
    __shared__ float2 smxy[P1N];    // A: prefetched mom; B: (mnx,mny)
    __shared__ float  s_w[19];      // w0[9], w1[9], kc

    const int tid = threadIdx.x;
    const int bx = blockIdx.x, by = blockIdx.y;
    const int tx0 = bx * TX;
    const int ty0 = by * TY;
    const bool interior = (bx >= 1) & (bx <= GBX - 2) & (by >= 1) & (by <= GBY - 2);

    if (tid == 0) {
        float ssum = 0.0f;
        #pragma unroll
        for (int j = 0; j < 36; ++j) ssum += fabsf(kern[j]);
        s_w[18] = 1.0f / ssum;
        #pragma unroll
        for (int j = 0; j < 9; ++j) {
            s_w[j]     = kern[j] + kern[9 + j];
            s_w[9 + j] = 0.5f * (kern[18 + j] + kern[27 + j]);
        }
    }

    // ---- Phase A: stage src (40x20) + prefetch mom (34x18) ----
    if (interior) {
        const float4* m4 = (const float4*)mass;
        const float4* a4 = (const float4*)A;
        const float4* f4 = (const float4*)force;
        const int c0 = (tx0 - 4) >> 2;
        for (int i = tid; i < SRCY * SRCX / 4; i += 256) {   // 200 float4
            int r = i / (SRCX / 4), c = i - r * (SRCX / 4);
            int g4 = (ty0 - 2 + r) * (Ww / 4) + c0 + c;
            float4 m = m4[g4], a = a4[g4];
            float4 fx = f4[g4], fy = f4[HW / 4 + g4];
            float hx = fmaf(fx.x, fx.x, fy.x * fy.x);
            float hy = fmaf(fx.y, fx.y, fy.y * fy.y);
            float hz = fmaf(fx.z, fx.z, fy.z * fy.z);
            float hw = fmaf(fx.w, fx.w, fy.w * fy.w);
            float4 s;
            s.x = fmaf(a.x, m.x, hx * rsqrtf(fmaxf(hx, 1e-38f)));
            s.y = fmaf(a.y, m.y, hy * rsqrtf(fmaxf(hy, 1e-38f)));
            s.z = fmaf(a.z, m.z, hz * rsqrtf(fmaxf(hz, 1e-38f)));
            s.w = fmaf(a.w, m.w, hw * rsqrtf(fmaxf(hw, 1e-38f)));
            ((float4*)s_src)[i] = s;
        }
        for (int s = tid; s < P1N; s += 256) {
            int sy = s / P1X, sx = s - sy * P1X;
            int g = (ty0 + sy - 1) * Ww + tx0 + sx - 1;
            smxy[s] = make_float2(mom[g], mom[HW + g]);
        }
    } else {
        for (int i = tid; i < SRCY * SRCX; i += 256) {
            int r = i / SRCX, c = i - r * SRCX;
            int gx = tx0 - 4 + c; if (gx < 0) gx += Ww; else if (gx >= Ww) gx -= Ww;
            int gy = ty0 - 2 + r; if (gy < 0) gy += Hh; else if (gy >= Hh) gy -= Hh;
            int g = gy * Ww + gx;
            float m = mass[g], a = A[g];
            float fx = force[g], fy = force[HW + g];
            float h = fmaf(fx, fx, fy * fy);
            s_src[i] = fmaf(a, m, h * rsqrtf(fmaxf(h, 1e-38f)));
        }
        for (int s = tid; s < P1N; s += 256) {
            int sy = s / P1X, sx = s - sy * P1X;
            int gx = tx0 + sx - 1; if (gx < 0) gx += Ww; else if (gx >= Ww) gx -= Ww;
            int gy = ty0 + sy - 1; if (gy < 0) gy += Hh; else if (gy >= Hh) gy -= Hh;
            int g = gy * Ww + gx;
            smxy[s] = make_float2(mom[g], mom[HW + g]);
        }
    }
    __syncthreads();

    float w0[9], w1[9];
    #pragma unroll
    for (int j = 0; j < 9; ++j) { w0[j] = s_w[j]; w1[j] = s_w[9 + j]; }
    const float kc = s_w[18];
    // temp*log2(e) folded: exp(0.1*x) == exp2(C*x)
    const float CT   = 0.1f * 1.4426950408889634f;
    const float SQ2T = 0.70710678118654752f * 0.1f * 1.4426950408889634f;

    // ---- Phase B: physics + softmax for the 1-halo region (34x18) ----
    for (int s = tid; s < P1N; s += 256) {
        int sy = s / P1X, sx = s - sy * P1X;
        int p2 = (sy + 1) * SRCX + sx + 3;

        float nf0 = 0.0f, nf1 = 0.0f;
        #pragma unroll
        for (int r = 0; r < 3; ++r)
            #pragma unroll
            for (int c = 0; c < 3; ++c) {
                float v = s_src[p2 + (r - 1) * SRCX + (c - 1)];
                nf0 = fmaf(v, w0[r * 3 + c], nf0);
                nf1 = fmaf(v, w1[r * 3 + c], nf1);
            }

        int g;
        if (interior) {
            g = (ty0 + sy - 1) * Ww + tx0 + sx - 1;
        } else {
            int gx = tx0 + sx - 1; if (gx < 0) gx += Ww; else if (gx >= Ww) gx -= Ww;
            int gy = ty0 + sy - 1; if (gy < 0) gy += Hh; else if (gy >= Hh) gy -= Hh;
            g = gy * Ww + gx;
        }

        float2 mo = smxy[s];               // prefetched mom (smem hit)
        float fx = force[g], fy = force[HW + g];   // L1-warm from phase A
        float fnx = fx + (nf0 - fx) * kc;
        float fny = fy + (nf1 - fy) * kc;
        float ms = mass[g];                        // L1-warm from phase A

        bool alive = !(ms < 1e-8f);
        float mnx = alive ? (mo.x + fnx) : 0.0f;
        float mny = alive ? (mo.y + fny) : 0.0f;
        float inv_ms = __fdividef(1.0f, ms);
        float vx = alive ? (mnx * inv_ms) : 0.0f;
        float vy = alive ? (mny * inv_ms) : 0.0f;

        // base-2 logits: set {l0,l1,l2,l3,0,-l3,-l2,-l1,-l0}
        float sv = SQ2T * vx, sw = SQ2T * vy;
        float l0 = sv + sw;
        float l1 = CT * vy;
        float l2 = sw - sv;
        float l3 = CT * vx;

        float mx = fmaxf(fmaxf(fabsf(l0), fabsf(l1)), fmaxf(fabsf(l2), fabsf(l3)));
        float e0 = ex2(l0 - mx);
        float e1 = ex2(l1 - mx);
        float e2 = ex2(l2 - mx);
        float e3 = ex2(l3 - mx);
        float e4 = ex2(-mx);
        float e5 = ex2(-l3 - mx);
        float e6 = ex2(-l2 - mx);
        float e7 = ex2(-l1 - mx);
        float e8 = ex2(-l0 - mx);
        float inv = __fdividef(1.0f,
            ((e0 + e1) + (e2 + e3)) + ((e4 + e5) + (e6 + e7)) + e8);

        sp[0][s] = e0 * inv;  sp[1][s] = e1 * inv;  sp[2][s] = e2 * inv;
        sp[3][s] = e3 * inv;  sp[4][s] = e4 * inv;  sp[5][s] = e5 * inv;
        sp[6][s] = e6 * inv;  sp[7][s] = e7 * inv;  sp[8][s] = e8 * inv;
        s_m[s]  = ms;
        smxy[s] = make_float2(mnx, mny);   // overwrite prefetched slot

        if (sx >= 1 && sx <= TX && sy >= 1 && sy <= TY) {
            out[3 * HW + g] = fnx;
            out[4 * HW + g] = fny;
        }
    }
    __syncthreads();

    // ---- Phase C: 3x3 gather, 2-row strip per thread, float2 state reads ----
    {
        const int ltx = tid & 31;
        const int lty = tid >> 5;
        const int oyA = lty * 2;
        float amA = 0.f, axA = 0.f, ayA = 0.f;
        float amB = 0.f, axB = 0.f, ayB = 0.f;

        #pragma unroll
        for (int r = 0; r < 4; ++r) {
            int rb = (oyA + r) * P1X + ltx;
            float  qm0 = s_m[rb], qm1 = s_m[rb + 1], qm2 = s_m[rb + 2];
            float2 q0 = smxy[rb], q1 = smxy[rb + 1], q2 = smxy[rb + 2];

            if (r <= 2) {   // pixel A, dy = r-1, plane base (2-r)*3
                float p;
                p = sp[(2 - r) * 3 + 0][rb + 2];
                amA = fmaf(qm2, p, amA); axA = fmaf(q2.x, p, axA); ayA = fmaf(q2.y, p, ayA);
                p = sp[(2 - r) * 3 + 1][rb + 1];
                amA = fmaf(qm1, p, amA); axA = fmaf(q1.x, p, axA); ayA = fmaf(q1.y, p, ayA);
                p = sp[(2 - r) * 3 + 2][rb];
                amA = fmaf(qm0, p, amA); axA = fmaf(q0.x, p, axA); ayA = fmaf(q0.y, p, ayA);
            }
            if (r >= 1) {   // pixel B, dy = r-2, plane base (3-r)*3
                float p;
                p = sp[(3 - r) * 3 + 0][rb + 2];
                amB = fmaf(qm2, p, amB); axB = fmaf(q2.x, p, axB); ayB = fmaf(q2.y, p, ayB);
                p = sp[(3 - r) * 3 + 1][rb + 1];
                amB = fmaf(qm1, p, amB); axB = fmaf(q1.x, p, axB); ayB = fmaf(q1.y, p, ayB);
                p = sp[(3 - r) * 3 + 2][rb];
                amB = fmaf(qm0, p, amB); axB = fmaf(q0.x, p, axB); ayB = fmaf(q0.y, p, ayB);
            }
        }

        int gA = (ty0 + oyA) * Ww + tx0 + ltx;
        out[gA]               = amA;
        out[HW + gA]          = axA;
        out[2 * HW + gA]      = ayA;
        out[gA + Ww]          = amB;
        out[HW + gA + Ww]     = axB;
        out[2 * HW + gA + Ww] = ayB;
    }
}

// ---------------------------------------------------------------------------
extern "C" void kernel_launch(void* const* d_in, const int* in_sizes, int n_in,
                              void* d_out, int out_size) {
    const float* mass = (const float*)d_in[0];   // (1,1,H,W)
    const float* mom  = (const float*)d_in[1];   // (2,1,H,W)
    const float* forc = (const float*)d_in[2];   // (2,1,H,W)
    const float* A    = (const float*)d_in[3];   // (1,1,H,W)
    const float* kern = (const float*)d_in[4];   // (4,1,3,3)
    float* out = (float*)d_out;                  // [new_mass | new_mom(2) | force(2)]

    dim3 grid(GBX, GBY);
    step_kernel<<<grid, 256>>>(mass, mom, forc, A, kern, out);
}

// round 17
// speedup vs baseline: 1.2049x; 1.0180x over previous
#include <cuda_runtime.h>

#define Hh 2048
#define Ww 2048
#define HW (Hh * Ww)
#define TX 32
#define TY 16
#define GBX (Ww / TX)      // 64
#define GBY (Hh / TY)      // 128
#define P1X 34
#define P1Y 18
#define P1N (P1X * P1Y)    // 612 : 1-halo region (props / state)
#define SRCX 40            // padded, 16B-aligned staging for src (2-halo + vec align)
#define SRCY 20

// fast exp2: exactly the MUFU.EX2 instruction, no compiler-flag dependence
__device__ __forceinline__ float ex2(float x) {
    float r;
    asm("ex2.approx.f32 %0, %1;" : "=f"(r) : "f"(x));
    return r;
}

// ---------------------------------------------------------------------------
// Fully fused step (R16 base = best kernel time 72.1us).
// R17 trims: (1) __stcs streaming stores for all outputs (write-once data;
// keep input halos resident in L2), (2) incremental (sy,sx) tracking in the
// B and mom-prefetch loops (256 = 7*34 + 18) killing the per-iteration
// div/mod, (3) force-out store hoisted right after fnx/fny.
// Locked lessons: 40-warp operating point (NO block caps — R7/R15 spills),
// conv weights in registers, plane-major props, scalar 2-row phase C,
// mom prefetched through smxy (A writes mom, B consumes + overwrites).
//  - global renormalization skipped (softmax sums to 1, MOVES are shifts)
//  - 4 conv kernels combined to 2 (k0+k1, 0.5*(k2+k3))
// ---------------------------------------------------------------------------
__global__ void __launch_bounds__(256) step_kernel(
    const float* __restrict__ mass, const float* __restrict__ mom,
    const float* __restrict__ force, const float* __restrict__ A,
    const float* __restrict__ kern, float* __restrict__ out)
{
    __shared__ float  s_src[SRCY * SRCX];
    __shared__ float  sp[9][P1N];   // normalized propagation weights
    __shared__ float  s_m[P1N];     // mass
    __shared__ float2 smxy[P1N];    // A: prefetched mom; B: (mnx,mny)
    __shared__ float  s_w[19];      // w0[9], w1[9], kc

    const int tid = threadIdx.x;
    const int bx = blockIdx.x, by = blockIdx.y;
    const int tx0 = bx * TX;
    const int ty0 = by * TY;
    const bool interior = (bx >= 1) & (bx <= GBX - 2) & (by >= 1) & (by <= GBY - 2);

    if (tid == 0) {
        float ssum = 0.0f;
        #pragma unroll
        for (int j = 0; j < 36; ++j) ssum += fabsf(kern[j]);
        s_w[18] = 1.0f / ssum;
        #pragma unroll
        for (int j = 0; j < 9; ++j) {
            s_w[j]     = kern[j] + kern[9 + j];
            s_w[9 + j] = 0.5f * (kern[18 + j] + kern[27 + j]);
        }
    }

    // initial (sy,sx) decomposition of tid for the P1-indexed loops
    const int sy0 = tid / P1X;
    const int sx0 = tid - sy0 * P1X;

    // ---- Phase A: stage src (40x20) + prefetch mom (34x18) ----
    if (interior) {
        const float4* m4 = (const float4*)mass;
        const float4* a4 = (const float4*)A;
        const float4* f4 = (const float4*)force;
        const int c0 = (tx0 - 4) >> 2;
        for (int i = tid; i < SRCY * SRCX / 4; i += 256) {   // 200 float4
            int r = i / (SRCX / 4), c = i - r * (SRCX / 4);
            int g4 = (ty0 - 2 + r) * (Ww / 4) + c0 + c;
            float4 m = m4[g4], a = a4[g4];
            float4 fx = f4[g4], fy = f4[HW / 4 + g4];
            float hx = fmaf(fx.x, fx.x, fy.x * fy.x);
            float hy = fmaf(fx.y, fx.y, fy.y * fy.y);
            float hz = fmaf(fx.z, fx.z, fy.z * fy.z);
            float hw = fmaf(fx.w, fx.w, fy.w * fy.w);
            float4 s;
            s.x = fmaf(a.x, m.x, hx * rsqrtf(fmaxf(hx, 1e-38f)));
            s.y = fmaf(a.y, m.y, hy * rsqrtf(fmaxf(hy, 1e-38f)));
            s.z = fmaf(a.z, m.z, hz * rsqrtf(fmaxf(hz, 1e-38f)));
            s.w = fmaf(a.w, m.w, hw * rsqrtf(fmaxf(hw, 1e-38f)));
            ((float4*)s_src)[i] = s;
        }
        {
            int sy = sy0, sx = sx0;
            const int gb = (ty0 - 1) * Ww + tx0 - 1;
            #pragma unroll 1
            for (int s = tid; s < P1N; s += 256) {
                int g = gb + sy * Ww + sx;
                smxy[s] = make_float2(mom[g], mom[HW + g]);
                sx += 18; sy += 7;
                if (sx >= P1X) { sx -= P1X; sy += 1; }
            }
        }
    } else {
        for (int i = tid; i < SRCY * SRCX; i += 256) {
            int r = i / SRCX, c = i - r * SRCX;
            int gx = tx0 - 4 + c; if (gx < 0) gx += Ww; else if (gx >= Ww) gx -= Ww;
            int gy = ty0 - 2 + r; if (gy < 0) gy += Hh; else if (gy >= Hh) gy -= Hh;
            int g = gy * Ww + gx;
            float m = mass[g], a = A[g];
            float fx = force[g], fy = force[HW + g];
            float h = fmaf(fx, fx, fy * fy);
            s_src[i] = fmaf(a, m, h * rsqrtf(fmaxf(h, 1e-38f)));
        }
        {
            int sy = sy0, sx = sx0;
            #pragma unroll 1
            for (int s = tid; s < P1N; s += 256) {
                int gx = tx0 + sx - 1; if (gx < 0) gx += Ww; else if (gx >= Ww) gx -= Ww;
                int gy = ty0 + sy - 1; if (gy < 0) gy += Hh; else if (gy >= Hh) gy -= Hh;
                int g = gy * Ww + gx;
                smxy[s] = make_float2(mom[g], mom[HW + g]);
                sx += 18; sy += 7;
                if (sx >= P1X) { sx -= P1X; sy += 1; }
            }
        }
    }
    __syncthreads();

    float w0[9], w1[9];
    #pragma unroll
    for (int j = 0; j < 9; ++j) { w0[j] = s_w[j]; w1[j] = s_w[9 + j]; }
    const float kc = s_w[18];
    // temp*log2(e) folded: exp(0.1*x) == exp2(C*x)
    const float CT   = 0.1f * 1.4426950408889634f;
    const float SQ2T = 0.70710678118654752f * 0.1f * 1.4426950408889634f;

    // ---- Phase B: physics + softmax for the 1-halo region (34x18) ----
    {
        int sy = sy0, sx = sx0;
        #pragma unroll 1
        for (int s = tid; s < P1N; s += 256) {
            int p2 = (sy + 1) * SRCX + sx + 3;

            float nf0 = 0.0f, nf1 = 0.0f;
            #pragma unroll
            for (int r = 0; r < 3; ++r)
                #pragma unroll
                for (int c = 0; c < 3; ++c) {
                    float v = s_src[p2 + (r - 1) * SRCX + (c - 1)];
                    nf0 = fmaf(v, w0[r * 3 + c], nf0);
                    nf1 = fmaf(v, w1[r * 3 + c], nf1);
                }

            int g;
            if (interior) {
                g = (ty0 + sy - 1) * Ww + tx0 + sx - 1;
            } else {
                int gx = tx0 + sx - 1; if (gx < 0) gx += Ww; else if (gx >= Ww) gx -= Ww;
                int gy = ty0 + sy - 1; if (gy < 0) gy += Hh; else if (gy >= Hh) gy -= Hh;
                g = gy * Ww + gx;
            }

            float2 mo = smxy[s];                       // prefetched mom (smem)
            float fx = force[g], fy = force[HW + g];   // L1-warm from phase A
            float fnx = fx + (nf0 - fx) * kc;
            float fny = fy + (nf1 - fy) * kc;
            float ms = mass[g];                        // L1-warm from phase A

            if (sx >= 1 && sx <= TX && sy >= 1 && sy <= TY) {
                __stcs(&out[3 * HW + g], fnx);
                __stcs(&out[4 * HW + g], fny);
            }

            bool alive = !(ms < 1e-8f);
            float mnx = alive ? (mo.x + fnx) : 0.0f;
            float mny = alive ? (mo.y + fny) : 0.0f;
            float inv_ms = __fdividef(1.0f, ms);
            float vx = alive ? (mnx * inv_ms) : 0.0f;
            float vy = alive ? (mny * inv_ms) : 0.0f;

            // base-2 logits: set {l0,l1,l2,l3,0,-l3,-l2,-l1,-l0}
            float sv = SQ2T * vx, sw = SQ2T * vy;
            float l0 = sv + sw;
            float l1 = CT * vy;
            float l2 = sw - sv;
            float l3 = CT * vx;

            float mx = fmaxf(fmaxf(fabsf(l0), fabsf(l1)), fmaxf(fabsf(l2), fabsf(l3)));
            float e0 = ex2(l0 - mx);
            float e1 = ex2(l1 - mx);
            float e2 = ex2(l2 - mx);
            float e3 = ex2(l3 - mx);
            float e4 = ex2(-mx);
            float e5 = ex2(-l3 - mx);
            float e6 = ex2(-l2 - mx);
            float e7 = ex2(-l1 - mx);
            float e8 = ex2(-l0 - mx);
            float inv = __fdividef(1.0f,
                ((e0 + e1) + (e2 + e3)) + ((e4 + e5) + (e6 + e7)) + e8);

            sp[0][s] = e0 * inv;  sp[1][s] = e1 * inv;  sp[2][s] = e2 * inv;
            sp[3][s] = e3 * inv;  sp[4][s] = e4 * inv;  sp[5][s] = e5 * inv;
            sp[6][s] = e6 * inv;  sp[7][s] = e7 * inv;  sp[8][s] = e8 * inv;
            s_m[s]  = ms;
            smxy[s] = make_float2(mnx, mny);   // overwrite prefetched slot

            sx += 18; sy += 7;
            if (sx >= P1X) { sx -= P1X; sy += 1; }
        }
    }
    __syncthreads();

    // ---- Phase C: 3x3 gather, 2-row strip per thread, float2 state reads ----
    {
        const int ltx = tid & 31;
        const int lty = tid >> 5;
        const int oyA = lty * 2;
        float amA = 0.f, axA = 0.f, ayA = 0.f;
        float amB = 0.f, axB = 0.f, ayB = 0.f;

        #pragma unroll
        for (int r = 0; r < 4; ++r) {
            int rb = (oyA + r) * P1X + ltx;
            float  qm0 = s_m[rb], qm1 = s_m[rb + 1], qm2 = s_m[rb + 2];
            float2 q0 = smxy[rb], q1 = smxy[rb + 1], q2 = smxy[rb + 2];

            if (r <= 2) {   // pixel A, dy = r-1, plane base (2-r)*3
                float p;
                p = sp[(2 - r) * 3 + 0][rb + 2];
                amA = fmaf(qm2, p, amA); axA = fmaf(q2.x, p, axA); ayA = fmaf(q2.y, p, ayA);
                p = sp[(2 - r) * 3 + 1][rb + 1];
                amA = fmaf(qm1, p, amA); axA = fmaf(q1.x, p, axA); ayA = fmaf(q1.y, p, ayA);
                p = sp[(2 - r) * 3 + 2][rb];
                amA = fmaf(qm0, p, amA); axA = fmaf(q0.x, p, axA); ayA = fmaf(q0.y, p, ayA);
            }
            if (r >= 1) {   // pixel B, dy = r-2, plane base (3-r)*3
                float p;
                p = sp[(3 - r) * 3 + 0][rb + 2];
                amB = fmaf(qm2, p, amB); axB = fmaf(q2.x, p, axB); ayB = fmaf(q2.y, p, ayB);
                p = sp[(3 - r) * 3 + 1][rb + 1];
                amB = fmaf(qm1, p, amB); axB = fmaf(q1.x, p, axB); ayB = fmaf(q1.y, p, ayB);
                p = sp[(3 - r) * 3 + 2][rb];
                amB = fmaf(qm0, p, amB); axB = fmaf(q0.x, p, axB); ayB = fmaf(q0.y, p, ayB);
            }
        }

        int gA = (ty0 + oyA) * Ww + tx0 + ltx;
        __stcs(&out[gA],               amA);
        __stcs(&out[HW + gA],          axA);
        __stcs(&out[2 * HW + gA],      ayA);
        __stcs(&out[gA + Ww],          amB);
        __stcs(&out[HW + gA + Ww],     axB);
        __stcs(&out[2 * HW + gA + Ww], ayB);
    }
}

// ---------------------------------------------------------------------------
extern "C" void kernel_launch(void* const* d_in, const int* in_sizes, int n_in,
                              void* d_out, int out_size) {
    const float* mass = (const float*)d_in[0];   // (1,1,H,W)
    const float* mom  = (const float*)d_in[1];   // (2,1,H,W)
    const float* forc = (const float*)d_in[2];   // (2,1,H,W)
    const float* A    = (const float*)d_in[3];   // (1,1,H,W)
    const float* kern = (const float*)d_in[4];   // (4,1,3,3)
    float* out = (float*)d_out;                  // [new_mass | new_mom(2) | force(2)]

    dim3 grid(GBX, GBY);
    step_kernel<<<grid, 256>>>(mass, mom, forc, A, kern, out);
}